// round 1
// baseline (speedup 1.0000x reference)
#include <cuda_runtime.h>
#include <cuda_bf16.h>
#include <math.h>

// Problem constants
#define T_TOKENS 4096   // B*S
#define DDIM     1024
#define MDIM     1408
#define NEXP     8
#define KTOP     2
#define BT       64                      // pair-tile
#define PAIRS_PAD 8704                   // 8192 + 8*64 padding slack
#define NTILES   (PAIRS_PAD / BT)        // 136

// ---------------- device scratch (static allocation only) ----------------
__device__ float g_H[(size_t)PAIRS_PAD * MDIM];   // SwiGLU hidden, ~49 MB
__device__ int   g_pair_tok[PAIRS_PAD];
__device__ float g_pair_p[PAIRS_PAD];
__device__ int   g_cnt[NEXP];
__device__ int   g_fill[NEXP];
__device__ int   g_segs[NEXP + 1];
__device__ int   g_tok_e[T_TOKENS * KTOP];
__device__ float g_tok_p[T_TOKENS * KTOP];

// ---------------- init: zero output, reset pair lists/counters ----------------
__global__ void init_kernel(float* __restrict__ out) {
    int i = blockIdx.x * blockDim.x + threadIdx.x;
    if (i < T_TOKENS * DDIM) out[i] = 0.0f;
    if (i < PAIRS_PAD) { g_pair_tok[i] = -1; g_pair_p[i] = 0.0f; }
    if (i < NEXP) g_cnt[i] = 0;
}

// ---------------- router: 1 warp per token ----------------
__global__ void router_kernel(const float* __restrict__ x,
                              const float* __restrict__ wg) {
    int warp = (blockIdx.x * blockDim.x + threadIdx.x) >> 5;
    int lane = threadIdx.x & 31;
    if (warp >= T_TOKENS) return;
    const float* xr = x + (size_t)warp * DDIM;
    float acc[NEXP];
#pragma unroll
    for (int e = 0; e < NEXP; e++) acc[e] = 0.0f;
    for (int d = lane; d < DDIM; d += 32) {
        float xv = xr[d];
        const float4* wr = (const float4*)(wg + (size_t)d * NEXP);
        float4 w0 = wr[0], w1 = wr[1];
        acc[0] += xv * w0.x; acc[1] += xv * w0.y;
        acc[2] += xv * w0.z; acc[3] += xv * w0.w;
        acc[4] += xv * w1.x; acc[5] += xv * w1.y;
        acc[6] += xv * w1.z; acc[7] += xv * w1.w;
    }
#pragma unroll
    for (int off = 16; off; off >>= 1)
#pragma unroll
        for (int e = 0; e < NEXP; e++)
            acc[e] += __shfl_xor_sync(0xffffffffu, acc[e], off);
    if (lane == 0) {
        int i0 = 0;
#pragma unroll
        for (int e = 1; e < NEXP; e++) if (acc[e] > acc[i0]) i0 = e;
        int i1 = (i0 == 0) ? 1 : 0;
#pragma unroll
        for (int e = 0; e < NEXP; e++)
            if (e != i0 && acc[e] > acc[i1]) i1 = e;
        float p1 = expf(acc[i1] - acc[i0]);
        float z  = 1.0f + p1;
        g_tok_e[warp * 2 + 0] = i0; g_tok_p[warp * 2 + 0] = 1.0f / z;
        g_tok_e[warp * 2 + 1] = i1; g_tok_p[warp * 2 + 1] = p1 / z;
        atomicAdd(&g_cnt[i0], 1);
        atomicAdd(&g_cnt[i1], 1);
    }
}

// ---------------- scan: padded per-expert segment starts ----------------
__global__ void scan_kernel() {
    int tot = 0;
    for (int e = 0; e < NEXP; e++) {
        g_segs[e] = tot;
        g_fill[e] = tot;
        tot += ((g_cnt[e] + BT - 1) / BT) * BT;
    }
    g_segs[NEXP] = tot;
}

// ---------------- scatter: expert-sorted pair list ----------------
__global__ void scatter_kernel() {
    int t = blockIdx.x * blockDim.x + threadIdx.x;
    if (t >= T_TOKENS) return;
#pragma unroll
    for (int k = 0; k < KTOP; k++) {
        int e = g_tok_e[t * 2 + k];
        int pos = atomicAdd(&g_fill[e], 1);
        g_pair_tok[pos] = t;
        g_pair_p[pos]   = g_tok_p[t * 2 + k];
    }
}

// ---------------- GEMM1: H = silu(X Wg) * (X Wu), 64x64x16 tiles ----------------
__global__ __launch_bounds__(256) void gemm1_kernel(const float* __restrict__ x,
                                                    const float* __restrict__ w_g,
                                                    const float* __restrict__ w_u) {
    __shared__ float Xs[16][BT];
    __shared__ float Gs[16][64];
    __shared__ float Us[16][64];
    __shared__ int   toks[BT];
    __shared__ int   s_e;

    int p0 = blockIdx.x * BT;
    int m0 = blockIdx.y * 64;
    if (threadIdx.x == 0) {
        int e = -1;
        if (p0 < g_segs[NEXP]) {
            e = 0;
            while (p0 >= g_segs[e + 1]) e++;
        }
        s_e = e;
    }
    if (threadIdx.x < BT) toks[threadIdx.x] = g_pair_tok[p0 + threadIdx.x];
    __syncthreads();
    int e = s_e;
    if (e < 0) return;
    const float* Wg = w_g + (size_t)e * DDIM * MDIM;
    const float* Wu = w_u + (size_t)e * DDIM * MDIM;

    int tx = threadIdx.x & 15;   // m-dir
    int ty = threadIdx.x >> 4;   // t-dir
    float ag[4][4], au[4][4];
#pragma unroll
    for (int i = 0; i < 4; i++)
#pragma unroll
        for (int j = 0; j < 4; j++) { ag[i][j] = 0.0f; au[i][j] = 0.0f; }

    int ld_pr = threadIdx.x >> 2;          // 0..63
    int ld_kq = (threadIdx.x & 3) * 4;     // 0,4,8,12
    int ld_k  = threadIdx.x >> 4;          // 0..15
    int ld_c  = (threadIdx.x & 15) * 4;    // 0..60
    int my_tok = toks[ld_pr];

    for (int kk = 0; kk < DDIM; kk += 16) {
        float4 v = make_float4(0.f, 0.f, 0.f, 0.f);
        if (my_tok >= 0)
            v = *(const float4*)(x + (size_t)my_tok * DDIM + kk + ld_kq);
        Xs[ld_kq + 0][ld_pr] = v.x;
        Xs[ld_kq + 1][ld_pr] = v.y;
        Xs[ld_kq + 2][ld_pr] = v.z;
        Xs[ld_kq + 3][ld_pr] = v.w;

        const float* gp = Wg + (size_t)(kk + ld_k) * MDIM + m0 + ld_c;
        const float* up = Wu + (size_t)(kk + ld_k) * MDIM + m0 + ld_c;
        *(float4*)&Gs[ld_k][ld_c] = *(const float4*)gp;
        *(float4*)&Us[ld_k][ld_c] = *(const float4*)up;
        __syncthreads();

#pragma unroll
        for (int k = 0; k < 16; k++) {
            float4 a  = *(const float4*)&Xs[k][ty * 4];
            float4 bg = *(const float4*)&Gs[k][tx * 4];
            float4 bu = *(const float4*)&Us[k][tx * 4];
            float av[4] = {a.x, a.y, a.z, a.w};
            float bgv[4] = {bg.x, bg.y, bg.z, bg.w};
            float buv[4] = {bu.x, bu.y, bu.z, bu.w};
#pragma unroll
            for (int i = 0; i < 4; i++)
#pragma unroll
                for (int j = 0; j < 4; j++) {
                    ag[i][j] += av[i] * bgv[j];
                    au[i][j] += av[i] * buv[j];
                }
        }
        __syncthreads();
    }

#pragma unroll
    for (int i = 0; i < 4; i++) {
        int p = p0 + ty * 4 + i;
        float4 hv;
        float g0 = ag[i][0], g1 = ag[i][1], g2 = ag[i][2], g3 = ag[i][3];
        hv.x = (g0 / (1.0f + expf(-g0))) * au[i][0];
        hv.y = (g1 / (1.0f + expf(-g1))) * au[i][1];
        hv.z = (g2 / (1.0f + expf(-g2))) * au[i][2];
        hv.w = (g3 / (1.0f + expf(-g3))) * au[i][3];
        *(float4*)&g_H[(size_t)p * MDIM + m0 + tx * 4] = hv;
    }
}

// ---------------- GEMM2: out[tok,:] += prob * H Wd, 64x64x16 tiles ----------------
__global__ __launch_bounds__(256) void gemm2_kernel(const float* __restrict__ w_d,
                                                    float* __restrict__ out) {
    __shared__ float Hs[16][BT];
    __shared__ float Ws[16][64];
    __shared__ int   toks[BT];
    __shared__ float probs[BT];
    __shared__ int   s_e;

    int p0 = blockIdx.x * BT;
    int d0 = blockIdx.y * 64;
    if (threadIdx.x == 0) {
        int e = -1;
        if (p0 < g_segs[NEXP]) {
            e = 0;
            while (p0 >= g_segs[e + 1]) e++;
        }
        s_e = e;
    }
    if (threadIdx.x < BT) {
        toks[threadIdx.x]  = g_pair_tok[p0 + threadIdx.x];
        probs[threadIdx.x] = g_pair_p[p0 + threadIdx.x];
    }
    __syncthreads();
    int e = s_e;
    if (e < 0) return;
    const float* Wd = w_d + (size_t)e * MDIM * DDIM;

    int tx = threadIdx.x & 15;
    int ty = threadIdx.x >> 4;
    float acc[4][4];
#pragma unroll
    for (int i = 0; i < 4; i++)
#pragma unroll
        for (int j = 0; j < 4; j++) acc[i][j] = 0.0f;

    int ld_pr = threadIdx.x >> 2;
    int ld_kq = (threadIdx.x & 3) * 4;
    int ld_k  = threadIdx.x >> 4;
    int ld_c  = (threadIdx.x & 15) * 4;

    for (int kk = 0; kk < MDIM; kk += 16) {
        float4 v = *(const float4*)(&g_H[(size_t)(p0 + ld_pr) * MDIM + kk + ld_kq]);
        Hs[ld_kq + 0][ld_pr] = v.x;
        Hs[ld_kq + 1][ld_pr] = v.y;
        Hs[ld_kq + 2][ld_pr] = v.z;
        Hs[ld_kq + 3][ld_pr] = v.w;

        const float* wp = Wd + (size_t)(kk + ld_k) * DDIM + d0 + ld_c;
        *(float4*)&Ws[ld_k][ld_c] = *(const float4*)wp;
        __syncthreads();

#pragma unroll
        for (int k = 0; k < 16; k++) {
            float4 a = *(const float4*)&Hs[k][ty * 4];
            float4 b = *(const float4*)&Ws[k][tx * 4];
            float av[4] = {a.x, a.y, a.z, a.w};
            float bv[4] = {b.x, b.y, b.z, b.w};
#pragma unroll
            for (int i = 0; i < 4; i++)
#pragma unroll
                for (int j = 0; j < 4; j++)
                    acc[i][j] += av[i] * bv[j];
        }
        __syncthreads();
    }

#pragma unroll
    for (int i = 0; i < 4; i++) {
        int r = ty * 4 + i;
        int tok = toks[r];
        if (tok < 0) continue;
        float p = probs[r];
        float* orow = out + (size_t)tok * DDIM + d0 + tx * 4;
#pragma unroll
        for (int j = 0; j < 4; j++)
            atomicAdd(&orow[j], p * acc[i][j]);
    }
}

// ---------------- launch ----------------
extern "C" void kernel_launch(void* const* d_in, const int* in_sizes, int n_in,
                              void* d_out, int out_size) {
    const float* x      = (const float*)d_in[0];
    const float* w_gate = (const float*)d_in[1];
    const float* w_g    = (const float*)d_in[2];
    const float* w_u    = (const float*)d_in[3];
    const float* w_d    = (const float*)d_in[4];
    float* out = (float*)d_out;

    init_kernel<<<(T_TOKENS * DDIM + 255) / 256, 256>>>(out);
    router_kernel<<<(T_TOKENS * 32 + 255) / 256, 256>>>(x, w_gate);
    scan_kernel<<<1, 1>>>();
    scatter_kernel<<<(T_TOKENS + 255) / 256, 256>>>();
    gemm1_kernel<<<dim3(NTILES, MDIM / 64), 256>>>(x, w_g, w_u);
    gemm2_kernel<<<dim3(NTILES, DDIM / 64), 256>>>(w_d, out);
}

// round 3
// speedup vs baseline: 3.8281x; 3.8281x over previous
#include <cuda_runtime.h>
#include <cuda_bf16.h>
#include <cstdint>
#include <math.h>

// ---------------- problem constants ----------------
#define T_TOKENS 4096
#define DDIM     1024
#define MDIM     1408
#define NEXP     8
#define BM       128
#define BN       64
#define PAIRS_PAD 9216
#define NTILES   (PAIRS_PAD / BM)     // 72
#define G1_CH    (DDIM / 32)          // 32
#define G2_CH    (MDIM / 32)          // 44

// ---------------- device scratch ----------------
__device__ __nv_bfloat16 g_Hh[(size_t)PAIRS_PAD * MDIM];
__device__ __nv_bfloat16 g_Hl[(size_t)PAIRS_PAD * MDIM];
__device__ int   g_pair_tok[PAIRS_PAD];
__device__ float g_pair_p[PAIRS_PAD];
__device__ int   g_cnt[NEXP];
__device__ int   g_fill[NEXP];
__device__ int   g_segs[NEXP + 1];
__device__ int   g_tok_e[T_TOKENS * 2];
__device__ float g_tok_p[T_TOKENS * 2];

// ---------------- helpers ----------------
__device__ __forceinline__ uint32_t smem_u32(const void* p) {
    uint32_t a;
    asm("{ .reg .u64 t; cvta.to.shared.u64 t, %1; cvt.u32.u64 %0, t; }" : "=r"(a) : "l"(p));
    return a;
}
__device__ __forceinline__ void ldsm_x4(uint32_t* r, uint32_t addr) {
    asm volatile("ldmatrix.sync.aligned.m8n8.x4.shared.b16 {%0,%1,%2,%3}, [%4];"
        : "=r"(r[0]), "=r"(r[1]), "=r"(r[2]), "=r"(r[3]) : "r"(addr));
}
__device__ __forceinline__ void ldsm_x4_t(uint32_t* r, uint32_t addr) {
    asm volatile("ldmatrix.sync.aligned.m8n8.x4.trans.shared.b16 {%0,%1,%2,%3}, [%4];"
        : "=r"(r[0]), "=r"(r[1]), "=r"(r[2]), "=r"(r[3]) : "r"(addr));
}
__device__ __forceinline__ void mma16816(float* d, const uint32_t* a, const uint32_t* b) {
    asm volatile("mma.sync.aligned.m16n8k16.row.col.f32.bf16.bf16.f32 "
        "{%0,%1,%2,%3},{%4,%5,%6,%7},{%8,%9},{%0,%1,%2,%3};"
        : "+f"(d[0]), "+f"(d[1]), "+f"(d[2]), "+f"(d[3])
        : "r"(a[0]), "r"(a[1]), "r"(a[2]), "r"(a[3]), "r"(b[0]), "r"(b[1]));
}
__device__ __forceinline__ void split4(float4 v, uint2& hi, uint2& lo) {
    __nv_bfloat16 h0 = __float2bfloat16(v.x), h1 = __float2bfloat16(v.y);
    __nv_bfloat16 h2 = __float2bfloat16(v.z), h3 = __float2bfloat16(v.w);
    __nv_bfloat162 a = {h0, h1}, b = {h2, h3};
    __nv_bfloat162 c = {__float2bfloat16(v.x - __bfloat162float(h0)),
                        __float2bfloat16(v.y - __bfloat162float(h1))};
    __nv_bfloat162 d = {__float2bfloat16(v.z - __bfloat162float(h2)),
                        __float2bfloat16(v.w - __bfloat162float(h3))};
    hi = make_uint2(*(uint32_t*)&a, *(uint32_t*)&b);
    lo = make_uint2(*(uint32_t*)&c, *(uint32_t*)&d);
}

// ---------------- small kernels ----------------
__global__ void init_kernel(float* __restrict__ out) {
    int i = blockIdx.x * blockDim.x + threadIdx.x;
    if (i < T_TOKENS * DDIM) out[i] = 0.0f;
    if (i < PAIRS_PAD) { g_pair_tok[i] = -1; g_pair_p[i] = 0.0f; }
    if (i < NEXP) g_cnt[i] = 0;
}

__global__ void router_kernel(const float* __restrict__ x, const float* __restrict__ wg) {
    int warp = (blockIdx.x * blockDim.x + threadIdx.x) >> 5;
    int lane = threadIdx.x & 31;
    if (warp >= T_TOKENS) return;
    const float* xr = x + (size_t)warp * DDIM;
    float acc[NEXP];
#pragma unroll
    for (int e = 0; e < NEXP; e++) acc[e] = 0.0f;
    for (int d = lane; d < DDIM; d += 32) {
        float xv = xr[d];
        const float4* wr = (const float4*)(wg + (size_t)d * NEXP);
        float4 w0 = wr[0], w1 = wr[1];
        acc[0] += xv * w0.x; acc[1] += xv * w0.y;
        acc[2] += xv * w0.z; acc[3] += xv * w0.w;
        acc[4] += xv * w1.x; acc[5] += xv * w1.y;
        acc[6] += xv * w1.z; acc[7] += xv * w1.w;
    }
#pragma unroll
    for (int off = 16; off; off >>= 1)
#pragma unroll
        for (int e = 0; e < NEXP; e++)
            acc[e] += __shfl_xor_sync(0xffffffffu, acc[e], off);
    if (lane == 0) {
        int i0 = 0;
#pragma unroll
        for (int e = 1; e < NEXP; e++) if (acc[e] > acc[i0]) i0 = e;
        int i1 = (i0 == 0) ? 1 : 0;
#pragma unroll
        for (int e = 0; e < NEXP; e++)
            if (e != i0 && acc[e] > acc[i1]) i1 = e;
        float p1 = expf(acc[i1] - acc[i0]);
        float z = 1.0f + p1;
        g_tok_e[warp * 2 + 0] = i0; g_tok_p[warp * 2 + 0] = 1.0f / z;
        g_tok_e[warp * 2 + 1] = i1; g_tok_p[warp * 2 + 1] = p1 / z;
        atomicAdd(&g_cnt[i0], 1);
        atomicAdd(&g_cnt[i1], 1);
    }
}

__global__ void scan_kernel() {
    int tot = 0;
    for (int e = 0; e < NEXP; e++) {
        g_segs[e] = tot;
        g_fill[e] = tot;
        tot += ((g_cnt[e] + BM - 1) / BM) * BM;
    }
    g_segs[NEXP] = tot;
}

__global__ void scatter_kernel() {
    int t = blockIdx.x * blockDim.x + threadIdx.x;
    if (t >= T_TOKENS) return;
#pragma unroll
    for (int k = 0; k < 2; k++) {
        int e = g_tok_e[t * 2 + k];
        int pos = atomicAdd(&g_fill[e], 1);
        g_pair_tok[pos] = t;
        g_pair_p[pos]   = g_tok_p[t * 2 + k];
    }
}

// ---------------- GEMM1 SMEM layout (bytes) ----------------
// A rows: 32 bf16 padded to 40 (80B stride) -> ldmatrix conflict-free
// B rows: 64 bf16 padded to 72 (144B stride)
#define S1_AH   0
#define S1_AL   10240
#define S1_BGH  20480
#define S1_BGL  25088
#define S1_BUH  29696
#define S1_BUL  34304
#define S1_TOK  38912
#define S1_SE   39424
#define S1_SIZE 39440

__global__ __launch_bounds__(256) void gemm1_kernel(const float* __restrict__ x,
                                                    const float* __restrict__ w_g,
                                                    const float* __restrict__ w_u) {
    __shared__ __align__(128) char sm[S1_SIZE];
    const uint32_t sb = smem_u32(sm);
    const int tid = threadIdx.x;
    const int lane = tid & 31, warp = tid >> 5;
    const int wm = warp >> 1, wn = warp & 1;
    const int p0 = blockIdx.x * BM;
    const int m0 = blockIdx.y * BN;

    if (tid == 0) {
        int e = -1;
        if (p0 < g_segs[NEXP]) { e = 0; while (p0 >= g_segs[e + 1]) e++; }
        *(int*)(sm + S1_SE) = e;
    }
    int* tokp = (int*)(sm + S1_TOK);
    if (tid < BM) tokp[tid] = g_pair_tok[p0 + tid];
    __syncthreads();
    const int e = *(int*)(sm + S1_SE);
    if (e < 0) return;

    const float* Wg = w_g + (size_t)e * DDIM * MDIM;
    const float* Wu = w_u + (size_t)e * DDIM * MDIM;

    // staging indices
    const int a_row = tid >> 3, a_kq = (tid & 7) * 4;       // +32 rows per i
    const int b_k = tid >> 4, b_nq = (tid & 15) * 4;        // +16 k per i
    const int tokA0 = tokp[a_row], tokA1 = tokp[a_row + 32],
              tokA2 = tokp[a_row + 64], tokA3 = tokp[a_row + 96];

    float accG[2][4][4], accU[2][4][4];
#pragma unroll
    for (int i = 0; i < 2; i++)
#pragma unroll
        for (int j = 0; j < 4; j++)
#pragma unroll
            for (int q = 0; q < 4; q++) { accG[i][j][q] = 0.f; accU[i][j][q] = 0.f; }

    // ldmatrix per-lane offsets
    const int lm_off = ((lane >> 3) & 1) * 8 + (lane & 7);  // row-in-16 (A: m, B: k)
    const int lm_hi  = (lane >> 4) * 8;                     // second-8 sel (A: k, B: n)
    const uint32_t aH0 = sb + S1_AH + (wm * 32 + lm_off) * 80 + lm_hi * 2;
    const uint32_t aL0 = sb + S1_AL + (wm * 32 + lm_off) * 80 + lm_hi * 2;
    const uint32_t bGH0 = sb + S1_BGH + lm_off * 144 + (wn * 32 + lm_hi) * 2;
    const uint32_t bGL0 = sb + S1_BGL + lm_off * 144 + (wn * 32 + lm_hi) * 2;
    const uint32_t bUH0 = sb + S1_BUH + lm_off * 144 + (wn * 32 + lm_hi) * 2;
    const uint32_t bUL0 = sb + S1_BUL + lm_off * 144 + (wn * 32 + lm_hi) * 2;

    float4 stA[4], stG[2], stU[2];

    // load chunk 0
    {
        const int kk = 0;
        stA[0] = tokA0 >= 0 ? *(const float4*)(x + (size_t)tokA0 * DDIM + kk + a_kq) : make_float4(0, 0, 0, 0);
        stA[1] = tokA1 >= 0 ? *(const float4*)(x + (size_t)tokA1 * DDIM + kk + a_kq) : make_float4(0, 0, 0, 0);
        stA[2] = tokA2 >= 0 ? *(const float4*)(x + (size_t)tokA2 * DDIM + kk + a_kq) : make_float4(0, 0, 0, 0);
        stA[3] = tokA3 >= 0 ? *(const float4*)(x + (size_t)tokA3 * DDIM + kk + a_kq) : make_float4(0, 0, 0, 0);
        stG[0] = *(const float4*)(Wg + (size_t)(kk + b_k) * MDIM + m0 + b_nq);
        stG[1] = *(const float4*)(Wg + (size_t)(kk + b_k + 16) * MDIM + m0 + b_nq);
        stU[0] = *(const float4*)(Wu + (size_t)(kk + b_k) * MDIM + m0 + b_nq);
        stU[1] = *(const float4*)(Wu + (size_t)(kk + b_k + 16) * MDIM + m0 + b_nq);
    }

    for (int ch = 0; ch < G1_CH; ch++) {
        // STS staged chunk
#pragma unroll
        for (int i = 0; i < 4; i++) {
            uint2 hi, lo; split4(stA[i], hi, lo);
            uint32_t off = (a_row + i * 32) * 80 + a_kq * 2;
            *(uint2*)(sm + S1_AH + off) = hi;
            *(uint2*)(sm + S1_AL + off) = lo;
        }
#pragma unroll
        for (int i = 0; i < 2; i++) {
            uint2 hi, lo;
            uint32_t off = (b_k + i * 16) * 144 + b_nq * 2;
            split4(stG[i], hi, lo);
            *(uint2*)(sm + S1_BGH + off) = hi;
            *(uint2*)(sm + S1_BGL + off) = lo;
            split4(stU[i], hi, lo);
            *(uint2*)(sm + S1_BUH + off) = hi;
            *(uint2*)(sm + S1_BUL + off) = lo;
        }
        __syncthreads();
        // prefetch next chunk into regs
        if (ch + 1 < G1_CH) {
            const int kk = (ch + 1) * 32;
            stA[0] = tokA0 >= 0 ? *(const float4*)(x + (size_t)tokA0 * DDIM + kk + a_kq) : make_float4(0, 0, 0, 0);
            stA[1] = tokA1 >= 0 ? *(const float4*)(x + (size_t)tokA1 * DDIM + kk + a_kq) : make_float4(0, 0, 0, 0);
            stA[2] = tokA2 >= 0 ? *(const float4*)(x + (size_t)tokA2 * DDIM + kk + a_kq) : make_float4(0, 0, 0, 0);
            stA[3] = tokA3 >= 0 ? *(const float4*)(x + (size_t)tokA3 * DDIM + kk + a_kq) : make_float4(0, 0, 0, 0);
            stG[0] = *(const float4*)(Wg + (size_t)(kk + b_k) * MDIM + m0 + b_nq);
            stG[1] = *(const float4*)(Wg + (size_t)(kk + b_k + 16) * MDIM + m0 + b_nq);
            stU[0] = *(const float4*)(Wu + (size_t)(kk + b_k) * MDIM + m0 + b_nq);
            stU[1] = *(const float4*)(Wu + (size_t)(kk + b_k + 16) * MDIM + m0 + b_nq);
        }
        // compute from SMEM
#pragma unroll
        for (int kh = 0; kh < 2; kh++) {
            uint32_t Ah[8], Al[8];
            ldsm_x4(Ah + 0, aH0 + kh * 32);
            ldsm_x4(Ah + 4, aH0 + 1280 + kh * 32);
            ldsm_x4(Al + 0, aL0 + kh * 32);
            ldsm_x4(Al + 4, aL0 + 1280 + kh * 32);
            uint32_t BgH[8], BgL[8], BuH[8], BuL[8];
            ldsm_x4_t(BgH + 0, bGH0 + kh * 2304);
            ldsm_x4_t(BgH + 4, bGH0 + kh * 2304 + 32);
            ldsm_x4_t(BgL + 0, bGL0 + kh * 2304);
            ldsm_x4_t(BgL + 4, bGL0 + kh * 2304 + 32);
            ldsm_x4_t(BuH + 0, bUH0 + kh * 2304);
            ldsm_x4_t(BuH + 4, bUH0 + kh * 2304 + 32);
            ldsm_x4_t(BuL + 0, bUL0 + kh * 2304);
            ldsm_x4_t(BuL + 4, bUL0 + kh * 2304 + 32);
#pragma unroll
            for (int mi = 0; mi < 2; mi++)
#pragma unroll
                for (int nf = 0; nf < 4; nf++) {
                    const uint32_t* bgh = &BgH[(nf >> 1) * 4 + (nf & 1) * 2];
                    const uint32_t* bgl = &BgL[(nf >> 1) * 4 + (nf & 1) * 2];
                    const uint32_t* buh = &BuH[(nf >> 1) * 4 + (nf & 1) * 2];
                    const uint32_t* bul = &BuL[(nf >> 1) * 4 + (nf & 1) * 2];
                    mma16816(accG[mi][nf], &Ah[mi * 4], bgh);
                    mma16816(accG[mi][nf], &Al[mi * 4], bgh);
                    mma16816(accG[mi][nf], &Ah[mi * 4], bgl);
                    mma16816(accU[mi][nf], &Ah[mi * 4], buh);
                    mma16816(accU[mi][nf], &Al[mi * 4], buh);
                    mma16816(accU[mi][nf], &Ah[mi * 4], bul);
                }
        }
        __syncthreads();
    }

    // epilogue: SwiGLU + hi/lo split store
    const int rg = lane >> 2, cg = (lane & 3) * 2;
#pragma unroll
    for (int mi = 0; mi < 2; mi++)
#pragma unroll
        for (int nf = 0; nf < 4; nf++) {
            const float* g = accG[mi][nf];
            const float* u = accU[mi][nf];
            int c = wn * 32 + nf * 8 + cg;
            size_t b0 = (size_t)(p0 + wm * 32 + mi * 16 + rg) * MDIM + m0 + c;
            size_t b1 = b0 + (size_t)8 * MDIM;
            float h0 = g[0] / (1.f + __expf(-g[0])) * u[0];
            float h1 = g[1] / (1.f + __expf(-g[1])) * u[1];
            float h2 = g[2] / (1.f + __expf(-g[2])) * u[2];
            float h3 = g[3] / (1.f + __expf(-g[3])) * u[3];
            __nv_bfloat16 a0 = __float2bfloat16(h0), a1 = __float2bfloat16(h1);
            __nv_bfloat16 a2 = __float2bfloat16(h2), a3 = __float2bfloat16(h3);
            __nv_bfloat162 hi0 = {a0, a1}, hi1 = {a2, a3};
            __nv_bfloat162 lo0 = {__float2bfloat16(h0 - __bfloat162float(a0)),
                                  __float2bfloat16(h1 - __bfloat162float(a1))};
            __nv_bfloat162 lo1 = {__float2bfloat16(h2 - __bfloat162float(a2)),
                                  __float2bfloat16(h3 - __bfloat162float(a3))};
            *(__nv_bfloat162*)&g_Hh[b0] = hi0;
            *(__nv_bfloat162*)&g_Hl[b0] = lo0;
            *(__nv_bfloat162*)&g_Hh[b1] = hi1;
            *(__nv_bfloat162*)&g_Hl[b1] = lo1;
        }
}

// ---------------- GEMM2 SMEM layout ----------------
#define S2_AH   0
#define S2_AL   10240
#define S2_BH   20480
#define S2_BL   25088
#define S2_TOK  29696
#define S2_PRB  30208
#define S2_SE   30720
#define S2_SIZE 30736

__global__ __launch_bounds__(256) void gemm2_kernel(const float* __restrict__ w_d,
                                                    float* __restrict__ out) {
    __shared__ __align__(128) char sm[S2_SIZE];
    const uint32_t sb = smem_u32(sm);
    const int tid = threadIdx.x;
    const int lane = tid & 31, warp = tid >> 5;
    const int wm = warp >> 1, wn = warp & 1;
    const int p0 = blockIdx.x * BM;
    const int d0 = blockIdx.y * BN;

    if (tid == 0) {
        int e = -1;
        if (p0 < g_segs[NEXP]) { e = 0; while (p0 >= g_segs[e + 1]) e++; }
        *(int*)(sm + S2_SE) = e;
    }
    int* tokp = (int*)(sm + S2_TOK);
    float* prbp = (float*)(sm + S2_PRB);
    if (tid < BM) {
        tokp[tid] = g_pair_tok[p0 + tid];
        prbp[tid] = g_pair_p[p0 + tid];
    }
    __syncthreads();
    const int e = *(int*)(sm + S2_SE);
    if (e < 0) return;

    const float* Wd = w_d + (size_t)e * MDIM * DDIM;

    const int a_row = tid >> 2, a_q = tid & 3;              // +64 rows per i
    const int b_k = tid >> 4, b_nq = (tid & 15) * 4;

    float acc[2][4][4];
#pragma unroll
    for (int i = 0; i < 2; i++)
#pragma unroll
        for (int j = 0; j < 4; j++)
#pragma unroll
            for (int q = 0; q < 4; q++) acc[i][j][q] = 0.f;

    const int lm_off = ((lane >> 3) & 1) * 8 + (lane & 7);
    const int lm_hi  = (lane >> 4) * 8;
    const uint32_t aH0 = sb + S2_AH + (wm * 32 + lm_off) * 80 + lm_hi * 2;
    const uint32_t aL0 = sb + S2_AL + (wm * 32 + lm_off) * 80 + lm_hi * 2;
    const uint32_t bH0 = sb + S2_BH + lm_off * 144 + (wn * 32 + lm_hi) * 2;
    const uint32_t bL0 = sb + S2_BL + lm_off * 144 + (wn * 32 + lm_hi) * 2;

    uint4 stAh[2], stAl[2];
    float4 stB[2];
    {
        const int kk = 0;
#pragma unroll
        for (int i = 0; i < 2; i++) {
            size_t g = (size_t)(p0 + a_row + i * 64) * MDIM + kk + a_q * 8;
            stAh[i] = *(const uint4*)&g_Hh[g];
            stAl[i] = *(const uint4*)&g_Hl[g];
        }
        stB[0] = *(const float4*)(Wd + (size_t)(kk + b_k) * DDIM + d0 + b_nq);
        stB[1] = *(const float4*)(Wd + (size_t)(kk + b_k + 16) * DDIM + d0 + b_nq);
    }

    for (int ch = 0; ch < G2_CH; ch++) {
#pragma unroll
        for (int i = 0; i < 2; i++) {
            uint32_t off = (a_row + i * 64) * 80 + a_q * 16;
            *(uint4*)(sm + S2_AH + off) = stAh[i];
            *(uint4*)(sm + S2_AL + off) = stAl[i];
        }
#pragma unroll
        for (int i = 0; i < 2; i++) {
            uint2 hi, lo; split4(stB[i], hi, lo);
            uint32_t off = (b_k + i * 16) * 144 + b_nq * 2;
            *(uint2*)(sm + S2_BH + off) = hi;
            *(uint2*)(sm + S2_BL + off) = lo;
        }
        __syncthreads();
        if (ch + 1 < G2_CH) {
            const int kk = (ch + 1) * 32;
#pragma unroll
            for (int i = 0; i < 2; i++) {
                size_t g = (size_t)(p0 + a_row + i * 64) * MDIM + kk + a_q * 8;
                stAh[i] = *(const uint4*)&g_Hh[g];
                stAl[i] = *(const uint4*)&g_Hl[g];
            }
            stB[0] = *(const float4*)(Wd + (size_t)(kk + b_k) * DDIM + d0 + b_nq);
            stB[1] = *(const float4*)(Wd + (size_t)(kk + b_k + 16) * DDIM + d0 + b_nq);
        }
#pragma unroll
        for (int kh = 0; kh < 2; kh++) {
            uint32_t Ah[8], Al[8];
            ldsm_x4(Ah + 0, aH0 + kh * 32);
            ldsm_x4(Ah + 4, aH0 + 1280 + kh * 32);
            ldsm_x4(Al + 0, aL0 + kh * 32);
            ldsm_x4(Al + 4, aL0 + 1280 + kh * 32);
            uint32_t BH[8], BL[8];
            ldsm_x4_t(BH + 0, bH0 + kh * 2304);
            ldsm_x4_t(BH + 4, bH0 + kh * 2304 + 32);
            ldsm_x4_t(BL + 0, bL0 + kh * 2304);
            ldsm_x4_t(BL + 4, bL0 + kh * 2304 + 32);
#pragma unroll
            for (int mi = 0; mi < 2; mi++)
#pragma unroll
                for (int nf = 0; nf < 4; nf++) {
                    const uint32_t* bh = &BH[(nf >> 1) * 4 + (nf & 1) * 2];
                    const uint32_t* bl = &BL[(nf >> 1) * 4 + (nf & 1) * 2];
                    mma16816(acc[mi][nf], &Ah[mi * 4], bh);
                    mma16816(acc[mi][nf], &Al[mi * 4], bh);
                    mma16816(acc[mi][nf], &Ah[mi * 4], bl);
                }
        }
        __syncthreads();
    }

    // epilogue: prob-scaled atomic combine
    const int rg = lane >> 2, cg = (lane & 3) * 2;
#pragma unroll
    for (int mi = 0; mi < 2; mi++)
#pragma unroll
        for (int nf = 0; nf < 4; nf++) {
            const float* d = acc[mi][nf];
            int c = wn * 32 + nf * 8 + cg;
            int r0 = wm * 32 + mi * 16 + rg, r1 = r0 + 8;
            int t0 = tokp[r0], t1 = tokp[r1];
            if (t0 >= 0) {
                float p = prbp[r0];
                float* o = out + (size_t)t0 * DDIM + d0 + c;
                atomicAdd(o, p * d[0]);
                atomicAdd(o + 1, p * d[1]);
            }
            if (t1 >= 0) {
                float p = prbp[r1];
                float* o = out + (size_t)t1 * DDIM + d0 + c;
                atomicAdd(o, p * d[2]);
                atomicAdd(o + 1, p * d[3]);
            }
        }
}

// ---------------- launch ----------------
extern "C" void kernel_launch(void* const* d_in, const int* in_sizes, int n_in,
                              void* d_out, int out_size) {
    const float* x      = (const float*)d_in[0];
    const float* w_gate = (const float*)d_in[1];
    const float* w_g    = (const float*)d_in[2];
    const float* w_u    = (const float*)d_in[3];
    const float* w_d    = (const float*)d_in[4];
    float* out = (float*)d_out;

    init_kernel<<<(T_TOKENS * DDIM + 255) / 256, 256>>>(out);
    router_kernel<<<(T_TOKENS * 32 + 255) / 256, 256>>>(x, w_gate);
    scan_kernel<<<1, 1>>>();
    scatter_kernel<<<(T_TOKENS + 255) / 256, 256>>>();
    gemm1_kernel<<<dim3(NTILES, MDIM / BN), 256>>>(x, w_g, w_u);
    gemm2_kernel<<<dim3(NTILES, DDIM / BN), 256>>>(w_d, out);
}

// round 4
// speedup vs baseline: 7.4278x; 1.9403x over previous
#include <cuda_runtime.h>
#include <cuda_bf16.h>
#include <cuda_fp16.h>
#include <cstdint>
#include <math.h>

// ---------------- problem constants ----------------
#define T_TOKENS 4096
#define DDIM     1024
#define MDIM     1408
#define NEXP     8
#define BM       128
#define BN       64
#define PAIRS_PAD 9216
#define NTILES   (PAIRS_PAD / BM)     // 72
#define G1_CH    (DDIM / 32)          // 32
#define G2_CH    (MDIM / 32)          // 44

// ---------------- device scratch ----------------
__device__ __half g_Hf[(size_t)PAIRS_PAD * MDIM];
__device__ int   g_pair_tok[PAIRS_PAD];
__device__ float g_pair_p[PAIRS_PAD];
__device__ int   g_cnt[NEXP];
__device__ int   g_fill[NEXP];
__device__ int   g_segs[NEXP + 1];
__device__ int   g_tok_e[T_TOKENS * 2];
__device__ float g_tok_p[T_TOKENS * 2];

// ---------------- helpers ----------------
__device__ __forceinline__ uint32_t smem_u32(const void* p) {
    uint32_t a;
    asm("{ .reg .u64 t; cvta.to.shared.u64 t, %1; cvt.u32.u64 %0, t; }" : "=r"(a) : "l"(p));
    return a;
}
__device__ __forceinline__ void ldsm_x4(uint32_t* r, uint32_t addr) {
    asm volatile("ldmatrix.sync.aligned.m8n8.x4.shared.b16 {%0,%1,%2,%3}, [%4];"
        : "=r"(r[0]), "=r"(r[1]), "=r"(r[2]), "=r"(r[3]) : "r"(addr));
}
__device__ __forceinline__ void ldsm_x4_t(uint32_t* r, uint32_t addr) {
    asm volatile("ldmatrix.sync.aligned.m8n8.x4.trans.shared.b16 {%0,%1,%2,%3}, [%4];"
        : "=r"(r[0]), "=r"(r[1]), "=r"(r[2]), "=r"(r[3]) : "r"(addr));
}
__device__ __forceinline__ void mma16816(float* d, const uint32_t* a, const uint32_t* b) {
    asm volatile("mma.sync.aligned.m16n8k16.row.col.f32.f16.f16.f32 "
        "{%0,%1,%2,%3},{%4,%5,%6,%7},{%8,%9},{%0,%1,%2,%3};"
        : "+f"(d[0]), "+f"(d[1]), "+f"(d[2]), "+f"(d[3])
        : "r"(a[0]), "r"(a[1]), "r"(a[2]), "r"(a[3]), "r"(b[0]), "r"(b[1]));
}
__device__ __forceinline__ uint2 cvt4(float4 v) {
    __half2 a = __floats2half2_rn(v.x, v.y);
    __half2 b = __floats2half2_rn(v.z, v.w);
    return make_uint2(*(uint32_t*)&a, *(uint32_t*)&b);
}

// ---------------- small kernels ----------------
__global__ void init_kernel(float* __restrict__ out) {
    int i = blockIdx.x * blockDim.x + threadIdx.x;
    if (i < T_TOKENS * DDIM) out[i] = 0.0f;
    if (i < PAIRS_PAD) { g_pair_tok[i] = -1; g_pair_p[i] = 0.0f; }
    if (i < NEXP) g_cnt[i] = 0;
}

__global__ void router_kernel(const float* __restrict__ x, const float* __restrict__ wg) {
    int warp = (blockIdx.x * blockDim.x + threadIdx.x) >> 5;
    int lane = threadIdx.x & 31;
    if (warp >= T_TOKENS) return;
    const float* xr = x + (size_t)warp * DDIM;
    float acc[NEXP];
#pragma unroll
    for (int e = 0; e < NEXP; e++) acc[e] = 0.0f;
    for (int d = lane; d < DDIM; d += 32) {
        float xv = xr[d];
        const float4* wr = (const float4*)(wg + (size_t)d * NEXP);
        float4 w0 = wr[0], w1 = wr[1];
        acc[0] += xv * w0.x; acc[1] += xv * w0.y;
        acc[2] += xv * w0.z; acc[3] += xv * w0.w;
        acc[4] += xv * w1.x; acc[5] += xv * w1.y;
        acc[6] += xv * w1.z; acc[7] += xv * w1.w;
    }
#pragma unroll
    for (int off = 16; off; off >>= 1)
#pragma unroll
        for (int e = 0; e < NEXP; e++)
            acc[e] += __shfl_xor_sync(0xffffffffu, acc[e], off);
    if (lane == 0) {
        int i0 = 0;
#pragma unroll
        for (int e = 1; e < NEXP; e++) if (acc[e] > acc[i0]) i0 = e;
        int i1 = (i0 == 0) ? 1 : 0;
#pragma unroll
        for (int e = 0; e < NEXP; e++)
            if (e != i0 && acc[e] > acc[i1]) i1 = e;
        float p1 = expf(acc[i1] - acc[i0]);
        float z = 1.0f + p1;
        g_tok_e[warp * 2 + 0] = i0; g_tok_p[warp * 2 + 0] = 1.0f / z;
        g_tok_e[warp * 2 + 1] = i1; g_tok_p[warp * 2 + 1] = p1 / z;
        atomicAdd(&g_cnt[i0], 1);
        atomicAdd(&g_cnt[i1], 1);
    }
}

__global__ void scan_kernel() {
    int tot = 0;
    for (int e = 0; e < NEXP; e++) {
        g_segs[e] = tot;
        g_fill[e] = tot;
        tot += ((g_cnt[e] + BM - 1) / BM) * BM;
    }
    g_segs[NEXP] = tot;
}

__global__ void scatter_kernel() {
    int t = blockIdx.x * blockDim.x + threadIdx.x;
    if (t >= T_TOKENS) return;
#pragma unroll
    for (int k = 0; k < 2; k++) {
        int e = g_tok_e[t * 2 + k];
        int pos = atomicAdd(&g_fill[e], 1);
        g_pair_tok[pos] = t;
        g_pair_p[pos]   = g_tok_p[t * 2 + k];
    }
}

// ---------------- GEMM1 SMEM layout (bytes) ----------------
// A rows: 32 fp16 padded to 40 (80B stride); B rows: 64 fp16 padded to 72 (144B)
#define S1_A    0
#define S1_BG   10240
#define S1_BU   14848
#define S1_TOK  19456
#define S1_SE   19968
#define S1_SIZE 19984

__global__ __launch_bounds__(256) void gemm1_kernel(const float* __restrict__ x,
                                                    const float* __restrict__ w_g,
                                                    const float* __restrict__ w_u) {
    __shared__ __align__(128) char sm[S1_SIZE];
    const uint32_t sb = smem_u32(sm);
    const int tid = threadIdx.x;
    const int lane = tid & 31, warp = tid >> 5;
    const int wm = warp >> 1, wn = warp & 1;
    const int p0 = blockIdx.x * BM;
    const int m0 = blockIdx.y * BN;

    if (tid == 0) {
        int e = -1;
        if (p0 < g_segs[NEXP]) { e = 0; while (p0 >= g_segs[e + 1]) e++; }
        *(int*)(sm + S1_SE) = e;
    }
    int* tokp = (int*)(sm + S1_TOK);
    if (tid < BM) tokp[tid] = g_pair_tok[p0 + tid];
    __syncthreads();
    const int e = *(int*)(sm + S1_SE);
    if (e < 0) return;

    const float* Wg = w_g + (size_t)e * DDIM * MDIM;
    const float* Wu = w_u + (size_t)e * DDIM * MDIM;

    const int a_row = tid >> 3, a_kq = (tid & 7) * 4;
    const int b_k = tid >> 4, b_nq = (tid & 15) * 4;
    const int tokA0 = tokp[a_row], tokA1 = tokp[a_row + 32],
              tokA2 = tokp[a_row + 64], tokA3 = tokp[a_row + 96];

    float accG[2][4][4], accU[2][4][4];
#pragma unroll
    for (int i = 0; i < 2; i++)
#pragma unroll
        for (int j = 0; j < 4; j++)
#pragma unroll
            for (int q = 0; q < 4; q++) { accG[i][j][q] = 0.f; accU[i][j][q] = 0.f; }

    const int lm_off = ((lane >> 3) & 1) * 8 + (lane & 7);
    const int lm_hi  = (lane >> 4) * 8;
    const uint32_t aA0 = sb + S1_A + (wm * 32 + lm_off) * 80 + lm_hi * 2;
    const uint32_t bG0 = sb + S1_BG + lm_off * 144 + (wn * 32 + lm_hi) * 2;
    const uint32_t bU0 = sb + S1_BU + lm_off * 144 + (wn * 32 + lm_hi) * 2;

    float4 stA[4], stG[2], stU[2];
    {
        const int kk = 0;
        stA[0] = tokA0 >= 0 ? *(const float4*)(x + (size_t)tokA0 * DDIM + kk + a_kq) : make_float4(0, 0, 0, 0);
        stA[1] = tokA1 >= 0 ? *(const float4*)(x + (size_t)tokA1 * DDIM + kk + a_kq) : make_float4(0, 0, 0, 0);
        stA[2] = tokA2 >= 0 ? *(const float4*)(x + (size_t)tokA2 * DDIM + kk + a_kq) : make_float4(0, 0, 0, 0);
        stA[3] = tokA3 >= 0 ? *(const float4*)(x + (size_t)tokA3 * DDIM + kk + a_kq) : make_float4(0, 0, 0, 0);
        stG[0] = *(const float4*)(Wg + (size_t)(kk + b_k) * MDIM + m0 + b_nq);
        stG[1] = *(const float4*)(Wg + (size_t)(kk + b_k + 16) * MDIM + m0 + b_nq);
        stU[0] = *(const float4*)(Wu + (size_t)(kk + b_k) * MDIM + m0 + b_nq);
        stU[1] = *(const float4*)(Wu + (size_t)(kk + b_k + 16) * MDIM + m0 + b_nq);
    }

    for (int ch = 0; ch < G1_CH; ch++) {
#pragma unroll
        for (int i = 0; i < 4; i++)
            *(uint2*)(sm + S1_A + (a_row + i * 32) * 80 + a_kq * 2) = cvt4(stA[i]);
#pragma unroll
        for (int i = 0; i < 2; i++) {
            uint32_t off = (b_k + i * 16) * 144 + b_nq * 2;
            *(uint2*)(sm + S1_BG + off) = cvt4(stG[i]);
            *(uint2*)(sm + S1_BU + off) = cvt4(stU[i]);
        }
        __syncthreads();
        if (ch + 1 < G1_CH) {
            const int kk = (ch + 1) * 32;
            stA[0] = tokA0 >= 0 ? *(const float4*)(x + (size_t)tokA0 * DDIM + kk + a_kq) : make_float4(0, 0, 0, 0);
            stA[1] = tokA1 >= 0 ? *(const float4*)(x + (size_t)tokA1 * DDIM + kk + a_kq) : make_float4(0, 0, 0, 0);
            stA[2] = tokA2 >= 0 ? *(const float4*)(x + (size_t)tokA2 * DDIM + kk + a_kq) : make_float4(0, 0, 0, 0);
            stA[3] = tokA3 >= 0 ? *(const float4*)(x + (size_t)tokA3 * DDIM + kk + a_kq) : make_float4(0, 0, 0, 0);
            stG[0] = *(const float4*)(Wg + (size_t)(kk + b_k) * MDIM + m0 + b_nq);
            stG[1] = *(const float4*)(Wg + (size_t)(kk + b_k + 16) * MDIM + m0 + b_nq);
            stU[0] = *(const float4*)(Wu + (size_t)(kk + b_k) * MDIM + m0 + b_nq);
            stU[1] = *(const float4*)(Wu + (size_t)(kk + b_k + 16) * MDIM + m0 + b_nq);
        }
#pragma unroll
        for (int kh = 0; kh < 2; kh++) {
            uint32_t A[8];
            ldsm_x4(A + 0, aA0 + kh * 32);
            ldsm_x4(A + 4, aA0 + 1280 + kh * 32);
            uint32_t Bg[8], Bu[8];
            ldsm_x4_t(Bg + 0, bG0 + kh * 2304);
            ldsm_x4_t(Bg + 4, bG0 + kh * 2304 + 32);
            ldsm_x4_t(Bu + 0, bU0 + kh * 2304);
            ldsm_x4_t(Bu + 4, bU0 + kh * 2304 + 32);
#pragma unroll
            for (int mi = 0; mi < 2; mi++)
#pragma unroll
                for (int nf = 0; nf < 4; nf++) {
                    const uint32_t* bg = &Bg[(nf >> 1) * 4 + (nf & 1) * 2];
                    const uint32_t* bu = &Bu[(nf >> 1) * 4 + (nf & 1) * 2];
                    mma16816(accG[mi][nf], &A[mi * 4], bg);
                    mma16816(accU[mi][nf], &A[mi * 4], bu);
                }
        }
        __syncthreads();
    }

    // epilogue: SwiGLU -> fp16 store
    const int rg = lane >> 2, cg = (lane & 3) * 2;
#pragma unroll
    for (int mi = 0; mi < 2; mi++)
#pragma unroll
        for (int nf = 0; nf < 4; nf++) {
            const float* g = accG[mi][nf];
            const float* u = accU[mi][nf];
            int c = wn * 32 + nf * 8 + cg;
            size_t b0 = (size_t)(p0 + wm * 32 + mi * 16 + rg) * MDIM + m0 + c;
            size_t b1 = b0 + (size_t)8 * MDIM;
            float h0 = g[0] / (1.f + __expf(-g[0])) * u[0];
            float h1 = g[1] / (1.f + __expf(-g[1])) * u[1];
            float h2 = g[2] / (1.f + __expf(-g[2])) * u[2];
            float h3 = g[3] / (1.f + __expf(-g[3])) * u[3];
            *(__half2*)&g_Hf[b0] = __floats2half2_rn(h0, h1);
            *(__half2*)&g_Hf[b1] = __floats2half2_rn(h2, h3);
        }
}

// ---------------- GEMM2 SMEM layout ----------------
#define S2_A    0
#define S2_B    10240
#define S2_TOK  14848
#define S2_PRB  15360
#define S2_SE   15872
#define S2_SIZE 15888

__global__ __launch_bounds__(256) void gemm2_kernel(const float* __restrict__ w_d,
                                                    float* __restrict__ out) {
    __shared__ __align__(128) char sm[S2_SIZE];
    const uint32_t sb = smem_u32(sm);
    const int tid = threadIdx.x;
    const int lane = tid & 31, warp = tid >> 5;
    const int wm = warp >> 1, wn = warp & 1;
    const int p0 = blockIdx.x * BM;
    const int d0 = blockIdx.y * BN;

    if (tid == 0) {
        int e = -1;
        if (p0 < g_segs[NEXP]) { e = 0; while (p0 >= g_segs[e + 1]) e++; }
        *(int*)(sm + S2_SE) = e;
    }
    int* tokp = (int*)(sm + S2_TOK);
    float* prbp = (float*)(sm + S2_PRB);
    if (tid < BM) {
        tokp[tid] = g_pair_tok[p0 + tid];
        prbp[tid] = g_pair_p[p0 + tid];
    }
    __syncthreads();
    const int e = *(int*)(sm + S2_SE);
    if (e < 0) return;

    const float* Wd = w_d + (size_t)e * MDIM * DDIM;

    const int a_row = tid >> 2, a_q = tid & 3;
    const int b_k = tid >> 4, b_nq = (tid & 15) * 4;

    float acc[2][4][4];
#pragma unroll
    for (int i = 0; i < 2; i++)
#pragma unroll
        for (int j = 0; j < 4; j++)
#pragma unroll
            for (int q = 0; q < 4; q++) acc[i][j][q] = 0.f;

    const int lm_off = ((lane >> 3) & 1) * 8 + (lane & 7);
    const int lm_hi  = (lane >> 4) * 8;
    const uint32_t aA0 = sb + S2_A + (wm * 32 + lm_off) * 80 + lm_hi * 2;
    const uint32_t bB0 = sb + S2_B + lm_off * 144 + (wn * 32 + lm_hi) * 2;

    uint4 stA[2];
    float4 stB[2];
    {
        const int kk = 0;
#pragma unroll
        for (int i = 0; i < 2; i++)
            stA[i] = *(const uint4*)&g_Hf[(size_t)(p0 + a_row + i * 64) * MDIM + kk + a_q * 8];
        stB[0] = *(const float4*)(Wd + (size_t)(kk + b_k) * DDIM + d0 + b_nq);
        stB[1] = *(const float4*)(Wd + (size_t)(kk + b_k + 16) * DDIM + d0 + b_nq);
    }

    for (int ch = 0; ch < G2_CH; ch++) {
#pragma unroll
        for (int i = 0; i < 2; i++)
            *(uint4*)(sm + S2_A + (a_row + i * 64) * 80 + a_q * 16) = stA[i];
#pragma unroll
        for (int i = 0; i < 2; i++)
            *(uint2*)(sm + S2_B + (b_k + i * 16) * 144 + b_nq * 2) = cvt4(stB[i]);
        __syncthreads();
        if (ch + 1 < G2_CH) {
            const int kk = (ch + 1) * 32;
#pragma unroll
            for (int i = 0; i < 2; i++)
                stA[i] = *(const uint4*)&g_Hf[(size_t)(p0 + a_row + i * 64) * MDIM + kk + a_q * 8];
            stB[0] = *(const float4*)(Wd + (size_t)(kk + b_k) * DDIM + d0 + b_nq);
            stB[1] = *(const float4*)(Wd + (size_t)(kk + b_k + 16) * DDIM + d0 + b_nq);
        }
#pragma unroll
        for (int kh = 0; kh < 2; kh++) {
            uint32_t A[8];
            ldsm_x4(A + 0, aA0 + kh * 32);
            ldsm_x4(A + 4, aA0 + 1280 + kh * 32);
            uint32_t B[8];
            ldsm_x4_t(B + 0, bB0 + kh * 2304);
            ldsm_x4_t(B + 4, bB0 + kh * 2304 + 32);
#pragma unroll
            for (int mi = 0; mi < 2; mi++)
#pragma unroll
                for (int nf = 0; nf < 4; nf++)
                    mma16816(acc[mi][nf], &A[mi * 4], &B[(nf >> 1) * 4 + (nf & 1) * 2]);
        }
        __syncthreads();
    }

    // epilogue: prob-scaled atomic combine
    const int rg = lane >> 2, cg = (lane & 3) * 2;
#pragma unroll
    for (int mi = 0; mi < 2; mi++)
#pragma unroll
        for (int nf = 0; nf < 4; nf++) {
            const float* d = acc[mi][nf];
            int c = wn * 32 + nf * 8 + cg;
            int r0 = wm * 32 + mi * 16 + rg, r1 = r0 + 8;
            int t0 = tokp[r0], t1 = tokp[r1];
            if (t0 >= 0) {
                float p = prbp[r0];
                float* o = out + (size_t)t0 * DDIM + d0 + c;
                atomicAdd(o, p * d[0]);
                atomicAdd(o + 1, p * d[1]);
            }
            if (t1 >= 0) {
                float p = prbp[r1];
                float* o = out + (size_t)t1 * DDIM + d0 + c;
                atomicAdd(o, p * d[2]);
                atomicAdd(o + 1, p * d[3]);
            }
        }
}

// ---------------- launch ----------------
extern "C" void kernel_launch(void* const* d_in, const int* in_sizes, int n_in,
                              void* d_out, int out_size) {
    const float* x      = (const float*)d_in[0];
    const float* w_gate = (const float*)d_in[1];
    const float* w_g    = (const float*)d_in[2];
    const float* w_u    = (const float*)d_in[3];
    const float* w_d    = (const float*)d_in[4];
    float* out = (float*)d_out;

    init_kernel<<<(T_TOKENS * DDIM + 255) / 256, 256>>>(out);
    router_kernel<<<(T_TOKENS * 32 + 255) / 256, 256>>>(x, w_gate);
    scan_kernel<<<1, 1>>>();
    scatter_kernel<<<(T_TOKENS + 255) / 256, 256>>>();
    gemm1_kernel<<<dim3(NTILES, MDIM / BN), 256>>>(x, w_g, w_u);
    gemm2_kernel<<<dim3(NTILES, DDIM / BN), 256>>>(w_d, out);
}